// round 15
// baseline (speedup 1.0000x reference)
#include <cuda_runtime.h>
#include <cuda_bf16.h>
#include <stdint.h>
#include <math.h>

#define Bn 4
#define Cn 64
#define Hn 128
#define Wn 128
#define On 64
#define HW (Hn * Wn)

typedef unsigned long long ull;

// B weights pre-packed in MMA fragment order:
//   g_wB2[k][s][nt][lane] = uint4{ bh0, bh1, bl0, bl1 }  (deform, nt<8)
//   g_wA2[k][s][nt][lane] = same for offset/mask conv (nt<4, rows padded to 32)
__device__ __align__(16) uint4 g_wB2[9 * 4 * 8 * 32];   // 147456 B
__device__ __align__(16) uint4 g_wA2[9 * 4 * 4 * 32];   // 73728 B

// ---------------------------------------------------------------------------
// helpers
// ---------------------------------------------------------------------------
__device__ __forceinline__ uint32_t cvt_bf16x2(float lo, float hi) {
    uint32_t r;
    asm("cvt.rn.satfinite.bf16x2.f32 %0, %1, %2;" : "=r"(r) : "f"(hi), "f"(lo));
    return r;
}
__device__ __forceinline__ uint32_t smem_u32(const void* p) {
    uint32_t a;
    asm("{ .reg .u64 t; cvta.to.shared.u64 t, %1; cvt.u32.u64 %0, t; }"
        : "=r"(a) : "l"(p));
    return a;
}
__device__ __forceinline__ void sts128(uint32_t addr, const uint32_t* v) {
    asm volatile("st.shared.v4.b32 [%0], {%1,%2,%3,%4};"
                 :: "r"(addr), "r"(v[0]), "r"(v[1]), "r"(v[2]), "r"(v[3])
                 : "memory");
}
__device__ __forceinline__ float lds_f32(uint32_t addr) {
    float v; asm volatile("ld.shared.f32 %0, [%1];" : "=f"(v) : "r"(addr));
    return v;
}
__device__ __forceinline__ void sts_f32(uint32_t addr, float v) {
    asm volatile("st.shared.f32 [%0], %1;" :: "r"(addr), "f"(v) : "memory");
}
// ldmatrix x4: matrices in address order = mma A-frag order
__device__ __forceinline__ void ldmA(uint32_t* a, uint32_t addr) {
    asm volatile("ldmatrix.sync.aligned.m8n8.x4.shared.b16 {%0,%1,%2,%3}, [%4];"
                 : "=r"(a[0]), "=r"(a[1]), "=r"(a[2]), "=r"(a[3]) : "r"(addr));
}
// m16n8k16 row.col bf16 -> fp32
__device__ __forceinline__ void mma16816(float* d, const uint32_t* a,
                                         uint32_t b0, uint32_t b1) {
    asm volatile(
        "mma.sync.aligned.m16n8k16.row.col.f32.bf16.bf16.f32 "
        "{%0,%1,%2,%3}, {%4,%5,%6,%7}, {%8,%9}, {%0,%1,%2,%3};"
        : "+f"(d[0]), "+f"(d[1]), "+f"(d[2]), "+f"(d[3])
        : "r"(a[0]), "r"(a[1]), "r"(a[2]), "r"(a[3]), "r"(b0), "r"(b1));
}
__device__ __forceinline__ void split2(float v0, float v1,
                                       uint32_t& hw, uint32_t& lw) {
    hw = cvt_bf16x2(v0, v1);
    float h0 = __uint_as_float(hw << 16);
    float h1 = __uint_as_float(hw & 0xFFFF0000u);
    lw = cvt_bf16x2(v0 - h0, v1 - h1);
}

// ---------------------------------------------------------------------------
// Kernel P: pack weights into fragment order (unchanged).
// ---------------------------------------------------------------------------
__global__ void prep_w_kernel(const float* __restrict__ dw,
                              const float* __restrict__ ow,
                              const float* __restrict__ mw) {
    int idx = blockIdx.x * blockDim.x + threadIdx.x;
    const int NB = 9 * 4 * 8 * 32;     // 9216
    const int NA = 9 * 4 * 4 * 32;     // 4608
    if (idx < NB) {
        int lane = idx & 31;
        int nt = (idx >> 5) & 7;
        int s  = (idx >> 8) & 3;
        int k  = idx >> 10;
        int o  = nt * 8 + (lane >> 2);
        int c0 = (lane & 3) * 2 + s * 16;
        uint32_t h0, l0, h1, l1;
        split2(dw[(o * Cn + c0) * 9 + k],     dw[(o * Cn + c0 + 1) * 9 + k], h0, l0);
        split2(dw[(o * Cn + c0 + 8) * 9 + k], dw[(o * Cn + c0 + 9) * 9 + k], h1, l1);
        g_wB2[idx] = make_uint4(h0, h1, l0, l1);
    } else if (idx < NB + NA) {
        int e = idx - NB;
        int lane = e & 31;
        int nt = (e >> 5) & 3;
        int s  = (e >> 7) & 3;
        int k  = e >> 9;
        int o  = nt * 8 + (lane >> 2);
        int c0 = (lane & 3) * 2 + s * 16;
        float wv[4] = {0.f, 0.f, 0.f, 0.f};
        if (o < 18) {
            wv[0] = ow[(o * Cn + c0) * 9 + k];
            wv[1] = ow[(o * Cn + c0 + 1) * 9 + k];
            wv[2] = ow[(o * Cn + c0 + 8) * 9 + k];
            wv[3] = ow[(o * Cn + c0 + 9) * 9 + k];
        } else if (o < 27) {
            int om = o - 18;
            wv[0] = mw[(om * Cn + c0) * 9 + k];
            wv[1] = mw[(om * Cn + c0 + 1) * 9 + k];
            wv[2] = mw[(om * Cn + c0 + 8) * 9 + k];
            wv[3] = mw[(om * Cn + c0 + 9) * 9 + k];
        }
        uint32_t h0, l0, h1, l1;
        split2(wv[0], wv[1], h0, l0);
        split2(wv[2], wv[3], h1, l1);
        g_wA2[e] = make_uint4(h0, h1, l0, l1);
    }
}

// ---------------------------------------------------------------------------
// Fused kernel, 64-thread blocks (2 warps, 64 pixels), BARRIER-FREE.
// R15: __launch_bounds__(64, 8) -> 8 blocks/SM (16 warps), 192KB smem/SM,
// regs capped at exactly the 128 the R14 build already used.
// blockIdx.x = h*2 + seg; block covers pixels [seg*64, seg*64+64) of row h.
// SW128: addr = row*128 + (colBytes ^ ((row&7)<<4)).
// ---------------------------------------------------------------------------
#define S_AH  0
#define S_AL  8192
#define S_OFF 16384               // 32 ch x 64 px floats (27 used)
#define S_TOT 24576

__global__ __launch_bounds__(64, 8) void fused_kernel(
    const float* __restrict__ x,
    const float* __restrict__ offset_b,
    const float* __restrict__ mask_b,
    const float* __restrict__ deform_b,
    float* __restrict__ out)
{
    extern __shared__ char smem[];
    const uint32_t sb = smem_u32(smem);
    const int tid  = threadIdx.x;          // 0..63
    const int lane = tid & 31;
    const int wrp  = tid >> 5;             // 0..1
    const int h   = blockIdx.x >> 1;
    const int col0 = (blockIdx.x & 1) * 64;   // pixel-column base of this block
    const int b = blockIdx.y;

    const float* xb = x + (size_t)b * Cn * HW;

    const int lq = lane >> 2;              // 0..7
    const int lr = lane & 3;               // 0..3
    // ldmatrix lane roles
    const int g  = lane >> 3;              // 0..3
    const int r  = lane & 7;               // 0..7
    const uint32_t rsw   = (uint32_t)r << 4;
    const uint32_t kh16  = (uint32_t)(g >> 1) << 4;       // 0 or 16
    const uint32_t rowLd = (uint32_t)(wrp * 32 + (g & 1) * 8 + r) * 128;
    // gather write
    const uint32_t tsw    = (uint32_t)(tid & 7) << 4;
    const uint32_t rowoff = (uint32_t)tid * 128;

    // ======================= Phase 1: offset/mask conv ======================
    {
        float doff[2][4][4];
#pragma unroll
        for (int mt = 0; mt < 2; ++mt)
#pragma unroll
            for (int nt = 0; nt < 4; ++nt)
#pragma unroll
                for (int i = 0; i < 4; ++i) doff[mt][nt][i] = 0.f;

        for (int k = 0; k < 9; ++k) {
            __syncwarp();          // prev tap's ldmatrix done before overwrite
            int y  = h + k / 3 - 1;
            int xc = col0 + tid + k % 3 - 1;
            bool ok = (y >= 0) && (y < Hn) && (xc >= 0) && (xc < Wn);
            const float* xp = xb + y * Wn + xc;
#pragma unroll
            for (int q = 0; q < 8; ++q) {
                uint32_t hw4[4], lw4[4];
#pragma unroll
                for (int j = 0; j < 4; ++j) {
                    int c0 = q * 8 + j * 2;
                    float v0 = ok ? __ldg(xp + c0 * HW) : 0.f;
                    float v1 = ok ? __ldg(xp + (c0 + 1) * HW) : 0.f;
                    split2(v0, v1, hw4[j], lw4[j]);
                }
                uint32_t off = rowoff + (((uint32_t)(q * 16)) ^ tsw);
                sts128(sb + S_AH + off, hw4);
                sts128(sb + S_AL + off, lw4);
            }
            __syncwarp();
            const uint4* wB = g_wA2 + (k * 4) * 4 * 32 + lane;
#pragma unroll
            for (int s = 0; s < 4; ++s) {
                uint32_t kt = ((uint32_t)(s * 32) + kh16) ^ rsw;
                uint32_t ah[2][4], al[2][4];
#pragma unroll
                for (int mt = 0; mt < 2; ++mt) {
                    ldmA(ah[mt], sb + S_AH + rowLd + mt * 2048 + kt);
                    ldmA(al[mt], sb + S_AL + rowLd + mt * 2048 + kt);
                }
#pragma unroll
                for (int nt = 0; nt < 4; ++nt) {
                    uint4 bw = __ldg(&wB[(s * 4 + nt) * 32]);
#pragma unroll
                    for (int mt = 0; mt < 2; ++mt) {
                        mma16816(doff[mt][nt], ah[mt], bw.x, bw.y);
                        mma16816(doff[mt][nt], al[mt], bw.x, bw.y);
                        mma16816(doff[mt][nt], ah[mt], bw.z, bw.w);
                    }
                }
            }
        }
        // Epilogue: bias + sigmoid -> S_OFF (warp-private pixel slice)
#pragma unroll
        for (int nt = 0; nt < 4; ++nt) {
#pragma unroll
            for (int oi = 0; oi < 2; ++oi) {
                int o = nt * 8 + lr * 2 + oi;
                float bias = 0.f; bool sig = false;
                if (o < 18) bias = __ldg(offset_b + o);
                else if (o < 27) { bias = __ldg(mask_b + o - 18); sig = true; }
#pragma unroll
                for (int mt = 0; mt < 2; ++mt) {
                    int px0 = wrp * 32 + mt * 16 + lq;
#pragma unroll
                    for (int ri = 0; ri < 2; ++ri) {
                        float v = doff[mt][nt][ri * 2 + oi] + bias;
                        if (sig) v = 1.f / (1.f + __expf(-v));
                        sts_f32(sb + S_OFF + (uint32_t)(o * 64 + px0 + ri * 8) * 4, v);
                    }
                }
            }
        }
        __syncwarp();
    }

    // ========================= Phase 2: deform conv =========================
    float d[2][8][4];
#pragma unroll
    for (int mt = 0; mt < 2; ++mt)
#pragma unroll
        for (int nt = 0; nt < 8; ++nt)
#pragma unroll
            for (int i = 0; i < 4; ++i) d[mt][nt][i] = 0.f;

    for (int k = 0; k < 9; ++k) {
        __syncwarp();

        float dy = lds_f32(sb + S_OFF + (uint32_t)((2 * k) * 64 + tid) * 4);
        float dx = lds_f32(sb + S_OFF + (uint32_t)((2 * k + 1) * 64 + tid) * 4);
        float m  = lds_f32(sb + S_OFF + (uint32_t)((18 + k) * 64 + tid) * 4);

        float py = dy + (float)(k / 3 + h - 1);
        float px = dx + (float)(k % 3 + col0 + tid - 1);
        float y0f = floorf(py), x0f = floorf(px);
        float fy = py - y0f, fx = px - x0f;
        int y0 = (int)y0f, x0 = (int)x0f;
        int y1 = y0 + 1, x1 = x0 + 1;
        float wy0 = 1.f - fy, wx0 = 1.f - fx;
        float w00 = wy0 * wx0 * m;
        float w01 = wy0 * fx  * m;
        float w10 = fy  * wx0 * m;
        float w11 = fy  * fx  * m;
        bool vy0 = (y0 >= 0) && (y0 < Hn);
        bool vy1 = (y1 >= 0) && (y1 < Hn);
        bool vx0 = (x0 >= 0) && (x0 < Wn);
        bool vx1 = (x1 >= 0) && (x1 < Wn);
        if (!(vy0 && vx0)) w00 = 0.f;
        if (!(vy0 && vx1)) w01 = 0.f;
        if (!(vy1 && vx0)) w10 = 0.f;
        if (!(vy1 && vx1)) w11 = 0.f;
        int y0c = min(max(y0, 0), Hn - 1), y1c = min(max(y1, 0), Hn - 1);
        int x0c = min(max(x0, 0), Wn - 1), x1c = min(max(x1, 0), Wn - 1);
        int i00 = y0c * Wn + x0c, i01 = y0c * Wn + x1c;
        int i10 = y1c * Wn + x0c, i11 = y1c * Wn + x1c;

#pragma unroll
        for (int q = 0; q < 8; ++q) {
            uint32_t hw4[4], lw4[4];
#pragma unroll
            for (int j = 0; j < 4; ++j) {
                const float* xc0 = xb + (q * 8 + j * 2) * HW;
                const float* xc1 = xc0 + HW;
                float v0 = w00 * __ldg(xc0 + i00) + w01 * __ldg(xc0 + i01)
                         + w10 * __ldg(xc0 + i10) + w11 * __ldg(xc0 + i11);
                float v1 = w00 * __ldg(xc1 + i00) + w01 * __ldg(xc1 + i01)
                         + w10 * __ldg(xc1 + i10) + w11 * __ldg(xc1 + i11);
                split2(v0, v1, hw4[j], lw4[j]);
            }
            uint32_t off = rowoff + (((uint32_t)(q * 16)) ^ tsw);
            sts128(sb + S_AH + off, hw4);
            sts128(sb + S_AL + off, lw4);
        }
        __syncwarp();

        const uint4* wB = g_wB2 + (k * 4) * 8 * 32 + lane;
#pragma unroll
        for (int s = 0; s < 4; ++s) {
            uint32_t kt = ((uint32_t)(s * 32) + kh16) ^ rsw;
            uint32_t ah[2][4], al[2][4];
#pragma unroll
            for (int mt = 0; mt < 2; ++mt) {
                ldmA(ah[mt], sb + S_AH + rowLd + mt * 2048 + kt);
                ldmA(al[mt], sb + S_AL + rowLd + mt * 2048 + kt);
            }
#pragma unroll
            for (int nt = 0; nt < 8; ++nt) {
                uint4 bw = __ldg(&wB[(s * 8 + nt) * 32]);
#pragma unroll
                for (int mt = 0; mt < 2; ++mt) {
                    mma16816(d[mt][nt], ah[mt], bw.x, bw.y);
                    mma16816(d[mt][nt], al[mt], bw.x, bw.y);
                    mma16816(d[mt][nt], ah[mt], bw.z, bw.w);
                }
            }
        }
    }

    // epilogue: d[mt][nt][i] -> out[(b*64+o)*HW + h*Wn + col0 + px] + bias
#pragma unroll
    for (int nt = 0; nt < 8; ++nt) {
        int o0 = nt * 8 + lr * 2;
        float bb0 = __ldg(deform_b + o0);
        float bb1 = __ldg(deform_b + o0 + 1);
#pragma unroll
        for (int mt = 0; mt < 2; ++mt) {
            int px0 = wrp * 32 + mt * 16 + lq;
            float* o0p = out + ((size_t)(b * On + o0)) * HW + h * Wn + col0;
            float* o1p = o0p + HW;
            o0p[px0]     = d[mt][nt][0] + bb0;
            o1p[px0]     = d[mt][nt][1] + bb1;
            o0p[px0 + 8] = d[mt][nt][2] + bb0;
            o1p[px0 + 8] = d[mt][nt][3] + bb1;
        }
    }
}

// ---------------------------------------------------------------------------
extern "C" void kernel_launch(void* const* d_in, const int* in_sizes, int n_in,
                              void* d_out, int out_size) {
    const float* x        = (const float*)d_in[0];
    const float* offset_w = (const float*)d_in[1];
    const float* offset_b = (const float*)d_in[2];
    const float* mask_w   = (const float*)d_in[3];
    const float* mask_b   = (const float*)d_in[4];
    const float* deform_w = (const float*)d_in[5];
    const float* deform_b = (const float*)d_in[6];
    float* out = (float*)d_out;

    cudaFuncSetAttribute(fused_kernel,
                         cudaFuncAttributeMaxDynamicSharedMemorySize, S_TOT);

    prep_w_kernel<<<(9 * 4 * 8 * 32 + 9 * 4 * 4 * 32 + 255) / 256, 256>>>(
        deform_w, offset_w, mask_w);

    dim3 grid(Hn * 2, Bn);
    fused_kernel<<<grid, 64, S_TOT>>>(x, offset_b, mask_b, deform_b, out);
}